// round 5
// baseline (speedup 1.0000x reference)
#include <cuda_runtime.h>
#include <cstdint>

#define N_PROP  2000
#define N_CLS   81
#define N_SORT  2048
#define PAD     300
#define MASK_F  63504      // 28*28*81
#define MASK_F4 15876      // MASK_F / 4
#define SUPP_W  64         // u32 words per suppression row (2048 bits)
#define N_TILE  63         // ceil(N_PROP/32)

// ---------------- device scratch (no allocations allowed) ----------------
__device__ float4 g_boxes[N_PROP];                 // decoded+clipped argmax-class box, original order
__device__ unsigned long long g_keys[N_PROP];      // sort keys
__device__ int    g_sorted[N_SORT];                // sorted position -> original index
__device__ float4 g_sboxes[N_PROP];                // boxes in sorted order
__device__ unsigned g_supp[N_SORT * SUPP_W];       // suppression bitmask per sorted row (rows>=N_PROP zero)
__device__ int    g_keptpos[PAD];                  // sorted positions of first <=300 kept
__device__ int    g_numkept;

// ---------------- K1: per-proposal argmax / max-score / box decode ----------------
__global__ void k1_prep(const float* __restrict__ meta,
                        const float* __restrict__ deltas,
                        const float* __restrict__ props,
                        const float* __restrict__ scores) {
    int warp = (blockIdx.x * blockDim.x + threadIdx.x) >> 5;
    int lane = threadIdx.x & 31;
    if (warp >= N_PROP) return;

    const float* sc = scores + (size_t)warp * N_CLS;
    float bv = -1e30f; int bi = N_CLS; float ms = -1e30f;
    for (int c = lane; c < N_CLS; c += 32) {
        float s = sc[c];
        if (s > bv || (s == bv && c < bi)) { bv = s; bi = c; }
        if (c >= 1) ms = fmaxf(ms, s);
    }
    for (int off = 16; off; off >>= 1) {
        float ov = __shfl_down_sync(0xffffffffu, bv, off);
        int   oi = __shfl_down_sync(0xffffffffu, bi, off);
        float om = __shfl_down_sync(0xffffffffu, ms, off);
        if (ov > bv || (ov == bv && oi < bi)) { bv = ov; bi = oi; }
        ms = fmaxf(ms, om);
    }
    if (lane == 0) {
        float H = meta[0], W = meta[1], scale = meta[2];
        float x1 = props[warp*4+0] / scale, y1 = props[warp*4+1] / scale;
        float x2 = props[warp*4+2] / scale, y2 = props[warp*4+3] / scale;
        float a  = x2 - x1, b = y2 - y1;
        float cx = x1 + 0.5f*a, cy = y1 + 0.5f*b;
        const float* d = deltas + (size_t)warp * (4*N_CLS) + 4*bi;
        float pcx = d[0]*a + cx, pcy = d[1]*b + cy;
        float pw  = expf(d[2])*a, ph = expf(d[3])*b;
        float ox1 = fminf(fmaxf(pcx - 0.5f*pw, 0.f), W - 1.f);
        float oy1 = fminf(fmaxf(pcy - 0.5f*ph, 0.f), H - 1.f);
        float ox2 = fminf(fmaxf(pcx + 0.5f*pw, 0.f), W - 1.f);
        float oy2 = fminf(fmaxf(pcy + 0.5f*ph, 0.f), H - 1.f);
        g_boxes[warp] = make_float4(ox1, oy1, ox2, oy2);

        // key: score descending, index ascending on ties  == stable argsort(-score)
        unsigned u = __float_as_uint(ms);
        u = (u & 0x80000000u) ? ~u : (u | 0x80000000u);   // order-preserving map
        unsigned hi = ~u;                                  // flip for descending
        g_keys[warp] = ((unsigned long long)hi << 32) | (unsigned)warp;
    }
}

// ---------------- K2: single-block bitonic sort of 2048 u64 keys ----------------
__global__ void k2_sort() {
    __shared__ unsigned long long sk[N_SORT];
    int t = threadIdx.x;
    for (int i = t; i < N_SORT; i += 1024)
        sk[i] = (i < N_PROP) ? g_keys[i] : 0xFFFFFFFFFFFFFFFFull;
    __syncthreads();
    for (int k = 2; k <= N_SORT; k <<= 1) {
        for (int j = k >> 1; j > 0; j >>= 1) {
            for (int i = t; i < N_SORT; i += 1024) {
                int ixj = i ^ j;
                if (ixj > i) {
                    unsigned long long a = sk[i], b = sk[ixj];
                    bool up = ((i & k) == 0);
                    if (up ? (a > b) : (a < b)) { sk[i] = b; sk[ixj] = a; }
                }
            }
            __syncthreads();
        }
    }
    for (int i = t; i < N_PROP; i += 1024) {
        int idx = (int)(unsigned)(sk[i] & 0xFFFFFFFFull);
        g_sorted[i]  = idx;
        g_sboxes[i]  = g_boxes[idx];
    }
}

// ---------------- K3: suppression bit-matrix (iou > 0.5, j > i); rows >= N_PROP zeroed ----------------
__global__ void k3_supp() {
    __shared__ float sx1[N_PROP], sy1[N_PROP], sx2[N_PROP], sy2[N_PROP], sar[N_PROP];
    for (int i = threadIdx.x; i < N_PROP; i += blockDim.x) {
        float4 bb = g_sboxes[i];
        sx1[i] = bb.x; sy1[i] = bb.y; sx2[i] = bb.z; sy2[i] = bb.w;
        sar[i] = fmaxf(bb.z - bb.x, 0.f) * fmaxf(bb.w - bb.y, 0.f);
    }
    __syncthreads();
    int lane = threadIdx.x & 31;
    int wid  = threadIdx.x >> 5;          // 0..7
    int base = blockIdx.x * 16;           // 16 rows per block (grid covers N_SORT rows)
    for (int task = wid; task < 16 * SUPP_W; task += 8) {
        int rl = task >> 6;               // local row
        int w  = task & 63;               // word
        int ri = base + rl;
        int j  = w * 32 + lane;
        bool bit = false;
        if (j > ri && j < N_PROP && ri < N_PROP) {
            float ix1 = fmaxf(sx1[ri], sx1[j]);
            float iy1 = fmaxf(sy1[ri], sy1[j]);
            float ix2 = fminf(sx2[ri], sx2[j]);
            float iy2 = fminf(sy2[ri], sy2[j]);
            float inter = fmaxf(ix2 - ix1, 0.f) * fmaxf(iy2 - iy1, 0.f);
            float uni   = fmaxf(sar[ri] + sar[j] - inter, 1e-8f);
            bit = inter > 0.5f * uni;
        }
        unsigned word = __ballot_sync(0xffffffffu, bit);
        if (lane == 0) g_supp[ri * SUPP_W + w] = word;
    }
}

// ---------------- K4: sequential greedy NMS scan — smem double-buffered tiles ----------------
// Removed-set distributed: lane l owns words l (rem0) and l+32 (rem1). A tile = 32 boxes = one
// 32-bit word of the removed-set; curw replicates that word across lanes. Tile rows (32 x 64
// words = 8KB) are staged in shared memory, double-buffered: stage tile t+1 with 16 uint4
// LDG.128+STS.128 per lane (off-chain, MLP=16) while scanning tile t from the other buffer.
// Inner iteration: 3 LDS (two lane-words conflict-free + one broadcast for the replicated
// suppression word s — no shfl), serial chain = SHF + SAR + LOP3 (~12 cyc).
__global__ void k4_nms() {
    __shared__ unsigned sbuf[2][32 * SUPP_W];      // 2 x 8KB tile buffers
    __shared__ unsigned smrem[N_TILE + 1];
    const unsigned F = 0xffffffffu;
    int lane = threadIdx.x;
    unsigned rem0 = 0, rem1 = 0;

    // stage tile 0 into buffer 0
    {
        const uint4* src = reinterpret_cast<const uint4*>(g_supp);      // 16 uint4 per row
        uint4* dst = reinterpret_cast<uint4*>(sbuf[0]);
        #pragma unroll
        for (int j = 0; j < 16; j++) dst[j * 32 + lane] = src[j * 32 + lane];
    }
    __syncwarp();

    int kc = 0, ntiles = N_TILE;
    for (int t = 0; t < N_TILE; t++) {
        const unsigned* buf = sbuf[t & 1];
        // stage tile t+1 into the other buffer (rows (t+1)*32 .. +31; g_supp has 2048 rows)
        {
            const uint4* src = reinterpret_cast<const uint4*>(g_supp) + (size_t)(t + 1) * 32 * 16;
            uint4* dst = reinterpret_cast<uint4*>(sbuf[(t + 1) & 1]);
            #pragma unroll
            for (int j = 0; j < 16; j++) dst[j * 32 + lane] = src[j * 32 + lane];
        }
        // replicated removed word for this tile (rem complete through tile t-1)
        unsigned curw = __shfl_sync(F, (t < 32) ? rem0 : rem1, t & 31);

        #pragma unroll
        for (int d = 0; d < 32; d++) {
            unsigned m0 = buf[d * SUPP_W + lane];          // LDS, conflict-free
            unsigned m1 = buf[d * SUPP_W + 32 + lane];     // LDS, conflict-free
            unsigned s  = buf[d * SUPP_W + t];             // LDS broadcast (row d's word t)
            // m = all-ones if box (t*32+d) already removed (bit d of curw set)
            unsigned m = (unsigned)(((int)(curw << (31 - d))) >> 31);
            curw |= s  & ~m;                               // chain: SHF, SAR, LOP3
            rem0 |= m0 & ~m;
            rem1 |= m1 & ~m;
        }
        unsigned valid = (t < 62) ? 0xffffffffu : 0xffffu; // tile 62 covers boxes 1984..1999
        if (lane == 0) smrem[t] = curw;
        kc += __popc((~curw) & valid);
        __syncwarp();                                      // staging STS visible before next LDS
        if (kc >= PAD) { ntiles = t + 1; break; }
    }
    __syncwarp();

    // Reconstruct kept positions: popc + warp exclusive scan over tile words, enumerate bits.
    int total = 0;
    #pragma unroll
    for (int rnd = 0; rnd < 2; rnd++) {
        int idx = rnd * 32 + lane;
        unsigned valid = (idx < 62) ? 0xffffffffu : ((idx == 62) ? 0xffffu : 0u);
        unsigned kw = (idx < ntiles) ? ((~smrem[idx]) & valid) : 0u;
        int c = __popc(kw);
        int inc = c;
        #pragma unroll
        for (int o = 1; o < 32; o <<= 1) {
            int v = __shfl_up_sync(0xffffffffu, inc, o);
            if (lane >= o) inc += v;
        }
        int slot = total + inc - c;                 // exclusive prefix
        while (kw) {
            int b = __ffs(kw) - 1; kw &= kw - 1;
            if (slot < PAD) g_keptpos[slot] = idx * 32 + b;
            slot++;
        }
        total += __shfl_sync(0xffffffffu, inc, 31);
    }
    if (lane == 31) g_numkept = (total < PAD) ? total : PAD;
}

// ---------------- K5: gather/scatter outputs (DRAM-bound, float4) ----------------
__global__ void k5_out(const float* __restrict__ scores,
                       const float* __restrict__ masks,
                       float* __restrict__ out) {
    int r  = blockIdx.y;
    int nk = g_numkept;
    int src = -1;
    if (r < nk) src = g_sorted[g_keptpos[r]];

    int c = blockIdx.x * blockDim.x + threadIdx.x;
    if (c < MASK_F4) {
        float4 v = make_float4(0.f, 0.f, 0.f, 0.f);
        if (src >= 0)
            v = reinterpret_cast<const float4*>(masks)[(size_t)src * MASK_F4 + c];
        reinterpret_cast<float4*>(out + PAD*4 + PAD*N_CLS)[(size_t)r * MASK_F4 + c] = v;
    }
    if (blockIdx.x == 0) {
        int t = threadIdx.x;
        if (t < 4) {
            float v = 0.f;
            if (src >= 0) v = reinterpret_cast<const float*>(g_boxes)[src*4 + t];
            out[r*4 + t] = v;
        } else if (t < 4 + N_CLS) {
            int cc = t - 4;
            float v = 0.f;
            if (src >= 0) v = scores[(size_t)src * N_CLS + cc];
            out[PAD*4 + r*N_CLS + cc] = v;
        }
    }
}

// ---------------- launch ----------------
extern "C" void kernel_launch(void* const* d_in, const int* in_sizes, int n_in,
                              void* d_out, int out_size) {
    const float* meta    = (const float*)d_in[0];
    const float* deltas  = (const float*)d_in[1];
    const float* props   = (const float*)d_in[2];
    const float* scores  = (const float*)d_in[3];
    const float* masks   = (const float*)d_in[4];
    float* out = (float*)d_out;

    k1_prep<<<(N_PROP * 32 + 255) / 256, 256>>>(meta, deltas, props, scores);
    k2_sort<<<1, 1024>>>();
    k3_supp<<<N_SORT / 16, 256>>>();
    k4_nms<<<1, 32>>>();
    dim3 g5((MASK_F4 + 255) / 256, PAD);
    k5_out<<<g5, 256>>>(scores, masks, out);
}

// round 6
// speedup vs baseline: 1.1304x; 1.1304x over previous
#include <cuda_runtime.h>
#include <cstdint>

#define N_PROP  2000
#define N_CLS   81
#define N_SORT  2048
#define PAD     300
#define MASK_F  63504      // 28*28*81
#define MASK_F4 15876      // MASK_F / 4
#define SUPP_W  64         // u32 words per suppression row (2048 bits)
#define N_TILE  63         // ceil(N_PROP/32)
#define HTILE   16         // phase-1 horizon: maintain rem words 0..15 (512 boxes)

// ---------------- device scratch (no allocations allowed) ----------------
__device__ float4 g_boxes[N_PROP];
__device__ unsigned long long g_keys[N_PROP];
__device__ int    g_sorted[N_SORT];
__device__ float4 g_sboxes[N_PROP];
__device__ unsigned g_supp[N_SORT * SUPP_W];       // rows >= N_PROP zeroed
__device__ int    g_keptpos[PAD];
__device__ int    g_numkept;

// ---------------- K1: per-proposal argmax / max-score / box decode ----------------
__global__ void k1_prep(const float* __restrict__ meta,
                        const float* __restrict__ deltas,
                        const float* __restrict__ props,
                        const float* __restrict__ scores) {
    int warp = (blockIdx.x * blockDim.x + threadIdx.x) >> 5;
    int lane = threadIdx.x & 31;
    if (warp >= N_PROP) return;

    const float* sc = scores + (size_t)warp * N_CLS;
    float bv = -1e30f; int bi = N_CLS; float ms = -1e30f;
    for (int c = lane; c < N_CLS; c += 32) {
        float s = sc[c];
        if (s > bv || (s == bv && c < bi)) { bv = s; bi = c; }
        if (c >= 1) ms = fmaxf(ms, s);
    }
    for (int off = 16; off; off >>= 1) {
        float ov = __shfl_down_sync(0xffffffffu, bv, off);
        int   oi = __shfl_down_sync(0xffffffffu, bi, off);
        float om = __shfl_down_sync(0xffffffffu, ms, off);
        if (ov > bv || (ov == bv && oi < bi)) { bv = ov; bi = oi; }
        ms = fmaxf(ms, om);
    }
    if (lane == 0) {
        float H = meta[0], W = meta[1], scale = meta[2];
        float x1 = props[warp*4+0] / scale, y1 = props[warp*4+1] / scale;
        float x2 = props[warp*4+2] / scale, y2 = props[warp*4+3] / scale;
        float a  = x2 - x1, b = y2 - y1;
        float cx = x1 + 0.5f*a, cy = y1 + 0.5f*b;
        const float* d = deltas + (size_t)warp * (4*N_CLS) + 4*bi;
        float pcx = d[0]*a + cx, pcy = d[1]*b + cy;
        float pw  = expf(d[2])*a, ph = expf(d[3])*b;
        float ox1 = fminf(fmaxf(pcx - 0.5f*pw, 0.f), W - 1.f);
        float oy1 = fminf(fmaxf(pcy - 0.5f*ph, 0.f), H - 1.f);
        float ox2 = fminf(fmaxf(pcx + 0.5f*pw, 0.f), W - 1.f);
        float oy2 = fminf(fmaxf(pcy + 0.5f*ph, 0.f), H - 1.f);
        g_boxes[warp] = make_float4(ox1, oy1, ox2, oy2);

        unsigned u = __float_as_uint(ms);
        u = (u & 0x80000000u) ? ~u : (u | 0x80000000u);
        unsigned hi = ~u;
        g_keys[warp] = ((unsigned long long)hi << 32) | (unsigned)warp;
    }
}

// ---------------- K2: single-block bitonic sort, direct pair indexing (no idle threads) ----------------
__global__ void k2_sort() {
    __shared__ unsigned long long sk[N_SORT];
    int t = threadIdx.x;                   // 0..1023, one compare-exchange per substage
    for (int i = t; i < N_SORT; i += 1024)
        sk[i] = (i < N_PROP) ? g_keys[i] : 0xFFFFFFFFFFFFFFFFull;
    __syncthreads();
    for (int k = 2; k <= N_SORT; k <<= 1) {
        for (int j = k >> 1; j > 0; j >>= 1) {
            int i = ((t & ~(j - 1)) << 1) | (t & (j - 1));
            int p = i | j;
            unsigned long long a = sk[i], b = sk[p];
            bool up = ((i & k) == 0);
            if (up ? (a > b) : (a < b)) { sk[i] = b; sk[p] = a; }
            __syncthreads();
        }
    }
    for (int i = t; i < N_PROP; i += 1024) {
        int idx = (int)(unsigned)(sk[i] & 0xFFFFFFFFull);
        g_sorted[i]  = idx;
        g_sboxes[i]  = g_boxes[idx];
    }
}

// ---------------- K3: suppression bit-matrix (iou > 0.5, j > i); rows >= N_PROP zeroed ----------------
__global__ void k3_supp() {
    __shared__ float sx1[N_PROP], sy1[N_PROP], sx2[N_PROP], sy2[N_PROP], sar[N_PROP];
    for (int i = threadIdx.x; i < N_PROP; i += blockDim.x) {
        float4 bb = g_sboxes[i];
        sx1[i] = bb.x; sy1[i] = bb.y; sx2[i] = bb.z; sy2[i] = bb.w;
        sar[i] = fmaxf(bb.z - bb.x, 0.f) * fmaxf(bb.w - bb.y, 0.f);
    }
    __syncthreads();
    int lane = threadIdx.x & 31;
    int wid  = threadIdx.x >> 5;
    int base = blockIdx.x * 16;
    for (int task = wid; task < 16 * SUPP_W; task += 8) {
        int rl = task >> 6;
        int w  = task & 63;
        int ri = base + rl;
        int j  = w * 32 + lane;
        bool bit = false;
        if (j > ri && j < N_PROP && ri < N_PROP) {
            float ix1 = fmaxf(sx1[ri], sx1[j]);
            float iy1 = fmaxf(sy1[ri], sy1[j]);
            float ix2 = fminf(sx2[ri], sx2[j]);
            float iy2 = fminf(sy2[ri], sy2[j]);
            float inter = fmaxf(ix2 - ix1, 0.f) * fmaxf(iy2 - iy1, 0.f);
            float uni   = fmaxf(sar[ri] + sar[j] - inter, 1e-8f);
            bit = inter > 0.5f * uni;
        }
        unsigned word = __ballot_sync(0xffffffffu, bit);
        if (lane == 0) g_supp[ri * SUPP_W + w] = word;
    }
}

// sign-extended single-bit extract: all-ones if bit `pos` of v is set
__device__ __forceinline__ unsigned bitmask(unsigned v, int pos) {
    int m;
    asm("bfe.s32 %0, %1, %2, 1;" : "=r"(m) : "r"(v), "r"(pos));
    return (unsigned)m;
}

// ---------------- K4: greedy NMS — diagonal-block closure, horizon-limited rem ----------------
// Only the diagonal 32x32 block of the suppression matrix touches the serial chain
// (chain/step = BFE + LOP3, shfl input off-chain). Rem maintenance limited to words
// 0..HTILE-1 (all that's ever read before the ~tile-10 early exit); rare overflow path
// rebuilds full rem from recorded kept words and continues with full maintenance.
__global__ void k4_nms() {
    __shared__ unsigned smrem[N_TILE + 1];
    const unsigned F = 0xffffffffu;
    int lane = threadIdx.x;
    unsigned remlo = 0;                    // lane l (l<16) owns rem word l
    int kc = 0, ntiles = N_TILE;
    bool done = false;

    int w16 = lane & 15, r0 = lane & 16;   // rem-update assignment: word w16, row half r0
    unsigned diag = g_supp[(size_t)lane * SUPP_W];   // tile-0 diagonal words

    for (int t = 0; t < HTILE; t++) {
        int p0 = t * 32;
        unsigned curw = __shfl_sync(F, remlo, t);     // seed: rem word t
        unsigned mydiag = diag;
        diag = g_supp[(size_t)(p0 + 32 + lane) * SUPP_W + (t + 1)];  // prefetch next diag
        unsigned ld[16];                               // rem-update rows (hoisted LDGs)
        #pragma unroll
        for (int d = 0; d < 16; d++)
            ld[d] = g_supp[(size_t)(p0 + r0 + d) * SUPP_W + w16];

        #pragma unroll
        for (int d = 0; d < 32; d++) {                // serial closure, 8 cyc/step
            unsigned s = __shfl_sync(F, mydiag, d);
            curw |= s & ~bitmask(curw, d);
        }
        unsigned kw = ~curw;                           // tiles < 62 are full
        if (lane == 0) smrem[t] = curw;
        kc += __popc(kw);

        unsigned upd = 0;                              // rem words 0..15 update (off-chain)
        #pragma unroll
        for (int d = 0; d < 16; d++)
            upd |= ld[d] & bitmask(kw, r0 + d);
        upd |= __shfl_xor_sync(F, upd, 16);
        remlo |= upd;

        if (kc >= PAD) { ntiles = t + 1; done = true; break; }
    }

    if (!done) {
        // RARE: horizon exceeded. Rebuild full distributed rem from kept words so far.
        unsigned rem0 = 0, rem1 = 0;
        for (int tt = 0; tt < HTILE; tt++) {
            unsigned kw = ~smrem[tt];
            while (kw) {
                int d = __ffs(kw) - 1; kw &= kw - 1;
                const unsigned* row = g_supp + (size_t)(tt * 32 + d) * SUPP_W;
                rem0 |= row[lane]; rem1 |= row[32 + lane];
            }
        }
        for (int t = HTILE; t < N_TILE; t++) {
            int p0 = t * 32;
            unsigned curw = __shfl_sync(F, (t < 32) ? rem0 : rem1, t & 31);
            unsigned mydiag = g_supp[(size_t)(p0 + lane) * SUPP_W + t];
            #pragma unroll
            for (int d = 0; d < 32; d++) {
                unsigned s = __shfl_sync(F, mydiag, d);
                curw |= s & ~bitmask(curw, d);
            }
            unsigned valid = (t < 62) ? 0xffffffffu : 0xffffu;
            unsigned kw = (~curw) & valid;
            if (lane == 0) smrem[t] = curw;
            kc += __popc(kw);
            #pragma unroll 4
            for (int d = 0; d < 32; d++) {
                unsigned mm = bitmask(kw, d);
                const unsigned* row = g_supp + (size_t)(p0 + d) * SUPP_W;
                rem0 |= mm & row[lane]; rem1 |= mm & row[32 + lane];
            }
            if (kc >= PAD) { ntiles = t + 1; break; }
        }
    }
    __syncwarp();

    // Reconstruct kept positions: popc + warp exclusive scan + bit enumerate
    int total = 0;
    #pragma unroll
    for (int rnd = 0; rnd < 2; rnd++) {
        int idx = rnd * 32 + lane;
        unsigned valid = (idx < 62) ? 0xffffffffu : ((idx == 62) ? 0xffffu : 0u);
        unsigned kw = (idx < ntiles) ? ((~smrem[idx]) & valid) : 0u;
        int c = __popc(kw);
        int inc = c;
        #pragma unroll
        for (int o = 1; o < 32; o <<= 1) {
            int v = __shfl_up_sync(0xffffffffu, inc, o);
            if (lane >= o) inc += v;
        }
        int slot = total + inc - c;
        while (kw) {
            int b = __ffs(kw) - 1; kw &= kw - 1;
            if (slot < PAD) g_keptpos[slot] = idx * 32 + b;
            slot++;
        }
        total += __shfl_sync(0xffffffffu, inc, 31);
    }
    if (lane == 31) g_numkept = (total < PAD) ? total : PAD;
}

// ---------------- K5: gather/scatter outputs (DRAM-bound, float4) ----------------
__global__ void k5_out(const float* __restrict__ scores,
                       const float* __restrict__ masks,
                       float* __restrict__ out) {
    int r  = blockIdx.y;
    int nk = g_numkept;
    int src = -1;
    if (r < nk) src = g_sorted[g_keptpos[r]];

    int c = blockIdx.x * blockDim.x + threadIdx.x;
    if (c < MASK_F4) {
        float4 v = make_float4(0.f, 0.f, 0.f, 0.f);
        if (src >= 0)
            v = reinterpret_cast<const float4*>(masks)[(size_t)src * MASK_F4 + c];
        reinterpret_cast<float4*>(out + PAD*4 + PAD*N_CLS)[(size_t)r * MASK_F4 + c] = v;
    }
    if (blockIdx.x == 0) {
        int t = threadIdx.x;
        if (t < 4) {
            float v = 0.f;
            if (src >= 0) v = reinterpret_cast<const float*>(g_boxes)[src*4 + t];
            out[r*4 + t] = v;
        } else if (t < 4 + N_CLS) {
            int cc = t - 4;
            float v = 0.f;
            if (src >= 0) v = scores[(size_t)src * N_CLS + cc];
            out[PAD*4 + r*N_CLS + cc] = v;
        }
    }
}

// ---------------- launch ----------------
extern "C" void kernel_launch(void* const* d_in, const int* in_sizes, int n_in,
                              void* d_out, int out_size) {
    const float* meta    = (const float*)d_in[0];
    const float* deltas  = (const float*)d_in[1];
    const float* props   = (const float*)d_in[2];
    const float* scores  = (const float*)d_in[3];
    const float* masks   = (const float*)d_in[4];
    float* out = (float*)d_out;

    k1_prep<<<(N_PROP * 32 + 255) / 256, 256>>>(meta, deltas, props, scores);
    k2_sort<<<1, 1024>>>();
    k3_supp<<<N_SORT / 16, 256>>>();
    k4_nms<<<1, 32>>>();
    dim3 g5((MASK_F4 + 255) / 256, PAD);
    k5_out<<<g5, 256>>>(scores, masks, out);
}

// round 8
// speedup vs baseline: 1.1605x; 1.0266x over previous
#include <cuda_runtime.h>
#include <cstdint>

#define N_PROP  2000
#define N_CLS   81
#define N_SORT  2048
#define PAD     300
#define MASK_F  63504      // 28*28*81
#define MASK_F4 15876      // MASK_F / 4
#define SUPP_W  64         // u32 words per suppression row (2048 bits)
#define N_TILE  63         // ceil(N_PROP/32)
#define HTILE   16         // phase-1 horizon: maintain rem words 0..15 (512 boxes)

// ---------------- device scratch (no allocations allowed) ----------------
__device__ float4 g_boxes[N_PROP];
__device__ unsigned long long g_keys[N_PROP];
__device__ int    g_sorted[N_SORT];
__device__ float4 g_sboxes[N_PROP];
__device__ unsigned g_supp[N_SORT * SUPP_W];       // rows >= N_PROP zeroed
__device__ int    g_keptpos[PAD];
__device__ int    g_numkept;

// ---------------- K1: per-proposal argmax / max-score / box decode ----------------
__global__ void k1_prep(const float* __restrict__ meta,
                        const float* __restrict__ deltas,
                        const float* __restrict__ props,
                        const float* __restrict__ scores) {
    int warp = (blockIdx.x * blockDim.x + threadIdx.x) >> 5;
    int lane = threadIdx.x & 31;
    if (warp >= N_PROP) return;

    const float* sc = scores + (size_t)warp * N_CLS;
    float bv = -1e30f; int bi = N_CLS; float ms = -1e30f;
    for (int c = lane; c < N_CLS; c += 32) {
        float s = sc[c];
        if (s > bv || (s == bv && c < bi)) { bv = s; bi = c; }
        if (c >= 1) ms = fmaxf(ms, s);
    }
    for (int off = 16; off; off >>= 1) {
        float ov = __shfl_down_sync(0xffffffffu, bv, off);
        int   oi = __shfl_down_sync(0xffffffffu, bi, off);
        float om = __shfl_down_sync(0xffffffffu, ms, off);
        if (ov > bv || (ov == bv && oi < bi)) { bv = ov; bi = oi; }
        ms = fmaxf(ms, om);
    }
    if (lane == 0) {
        float H = meta[0], W = meta[1], scale = meta[2];
        float x1 = props[warp*4+0] / scale, y1 = props[warp*4+1] / scale;
        float x2 = props[warp*4+2] / scale, y2 = props[warp*4+3] / scale;
        float a  = x2 - x1, b = y2 - y1;
        float cx = x1 + 0.5f*a, cy = y1 + 0.5f*b;
        const float* d = deltas + (size_t)warp * (4*N_CLS) + 4*bi;
        float pcx = d[0]*a + cx, pcy = d[1]*b + cy;
        float pw  = expf(d[2])*a, ph = expf(d[3])*b;
        float ox1 = fminf(fmaxf(pcx - 0.5f*pw, 0.f), W - 1.f);
        float oy1 = fminf(fmaxf(pcy - 0.5f*ph, 0.f), H - 1.f);
        float ox2 = fminf(fmaxf(pcx + 0.5f*pw, 0.f), W - 1.f);
        float oy2 = fminf(fmaxf(pcy + 0.5f*ph, 0.f), H - 1.f);
        g_boxes[warp] = make_float4(ox1, oy1, ox2, oy2);

        unsigned u = __float_as_uint(ms);
        u = (u & 0x80000000u) ? ~u : (u | 0x80000000u);
        unsigned hi = ~u;
        g_keys[warp] = ((unsigned long long)hi << 32) | (unsigned)warp;
    }
}

// ---------------- K2: single-block bitonic sort, direct pair indexing ----------------
__global__ void k2_sort() {
    __shared__ unsigned long long sk[N_SORT];
    int t = threadIdx.x;
    for (int i = t; i < N_SORT; i += 1024)
        sk[i] = (i < N_PROP) ? g_keys[i] : 0xFFFFFFFFFFFFFFFFull;
    __syncthreads();
    for (int k = 2; k <= N_SORT; k <<= 1) {
        for (int j = k >> 1; j > 0; j >>= 1) {
            int i = ((t & ~(j - 1)) << 1) | (t & (j - 1));
            int p = i | j;
            unsigned long long a = sk[i], b = sk[p];
            bool up = ((i & k) == 0);
            if (up ? (a > b) : (a < b)) { sk[i] = b; sk[p] = a; }
            __syncthreads();
        }
    }
    for (int i = t; i < N_PROP; i += 1024) {
        int idx = (int)(unsigned)(sk[i] & 0xFFFFFFFFull);
        g_sorted[i]  = idx;
        g_sboxes[i]  = g_boxes[idx];
    }
}

// ---------------- K3: suppression bit-matrix (iou > 0.5, j > i); rows >= N_PROP zeroed ----------------
__global__ void k3_supp() {
    __shared__ float sx1[N_PROP], sy1[N_PROP], sx2[N_PROP], sy2[N_PROP], sar[N_PROP];
    for (int i = threadIdx.x; i < N_PROP; i += blockDim.x) {
        float4 bb = g_sboxes[i];
        sx1[i] = bb.x; sy1[i] = bb.y; sx2[i] = bb.z; sy2[i] = bb.w;
        sar[i] = fmaxf(bb.z - bb.x, 0.f) * fmaxf(bb.w - bb.y, 0.f);
    }
    __syncthreads();
    int lane = threadIdx.x & 31;
    int wid  = threadIdx.x >> 5;
    int base = blockIdx.x * 16;
    for (int task = wid; task < 16 * SUPP_W; task += 8) {
        int rl = task >> 6;
        int w  = task & 63;
        int ri = base + rl;
        int j  = w * 32 + lane;
        bool bit = false;
        if (j > ri && j < N_PROP && ri < N_PROP) {
            float ix1 = fmaxf(sx1[ri], sx1[j]);
            float iy1 = fmaxf(sy1[ri], sy1[j]);
            float ix2 = fminf(sx2[ri], sx2[j]);
            float iy2 = fminf(sy2[ri], sy2[j]);
            float inter = fmaxf(ix2 - ix1, 0.f) * fmaxf(iy2 - iy1, 0.f);
            float uni   = fmaxf(sar[ri] + sar[j] - inter, 1e-8f);
            bit = inter > 0.5f * uni;
        }
        unsigned word = __ballot_sync(0xffffffffu, bit);
        if (lane == 0) g_supp[ri * SUPP_W + w] = word;
    }
}

// sign-extended single-bit extract: all-ones if bit `pos` of v is set
__device__ __forceinline__ unsigned bitmask(unsigned v, int pos) {
    int m;
    asm("bfe.s32 %0, %1, %2, 1;" : "=r"(m) : "r"(v), "r"(pos));
    return (unsigned)m;
}

// ---------------- K4: greedy NMS — in-lane diagonal closure, NO shfl per box ----------------
// Every lane redundantly loads the 32 diagonal words of tile t (uniform addresses, L2
// broadcast) into registers; the 32-step greedy closure is then pure in-lane BFE+LOP3
// (8 cyc/step). Diagonal blocks are register-double-buffered and prefetched a tile ahead.
// Shfls remaining: 1 seed + 1 xor-combine per TILE. Rem maintenance over horizon words
// 0..15 only; rare overflow path rebuilds full rem and finishes with generic code.
__device__ __forceinline__ bool k4_tile(int t, unsigned (&dcur)[32], unsigned (&dnext)[32],
        unsigned &remlo, int &kc, unsigned* smrem, int lane, int w16, int r0) {
    const unsigned F = 0xffffffffu;
    int p0 = t * 32;
    // issue rem-update row loads (consumed after closure; off-chain)
    unsigned ld[16];
    #pragma unroll
    for (int d = 0; d < 16; d++)
        ld[d] = g_supp[(size_t)(p0 + r0 + d) * SUPP_W + w16];
    // prefetch NEXT tile's diagonal words (uniform across lanes; consumed next tile)
    #pragma unroll
    for (int d = 0; d < 32; d++)
        dnext[d] = g_supp[(size_t)(p0 + 32 + d) * SUPP_W + (t + 1)];
    unsigned curw = __shfl_sync(F, remlo, t);         // seed: rem word t (1 shfl/tile)
    #pragma unroll
    for (int d = 0; d < 32; d++)                      // serial closure: BFE+LOP3 per step
        curw |= dcur[d] & ~bitmask(curw, d);
    unsigned kw = ~curw;                              // phase-1 tiles are full
    if (lane == 0) smrem[t] = curw;
    kc += __popc(kw);
    unsigned upd = 0;                                 // rem words 0..15 update (off-chain)
    #pragma unroll
    for (int d = 0; d < 16; d++)
        upd |= ld[d] & bitmask(kw, r0 + d);
    upd |= __shfl_xor_sync(F, upd, 16);
    remlo |= upd;
    return kc >= PAD;
}

__global__ void k4_nms() {
    __shared__ unsigned smrem[N_TILE + 1];
    const unsigned F = 0xffffffffu;
    int lane = threadIdx.x;
    unsigned remlo = 0;
    int kc = 0, ntiles = N_TILE;
    bool done = false;
    int w16 = lane & 15, r0 = lane & 16;

    unsigned dA[32], dB[32];
    #pragma unroll
    for (int d = 0; d < 32; d++)                      // tile 0 diagonal (word 0 of rows 0..31)
        dA[d] = g_supp[(size_t)d * SUPP_W];

    for (int t = 0; t < HTILE; t += 2) {              // two-tile unroll keeps indices constant
        if (k4_tile(t,     dA, dB, remlo, kc, smrem, lane, w16, r0)) { ntiles = t + 1; done = true; break; }
        if (k4_tile(t + 1, dB, dA, remlo, kc, smrem, lane, w16, r0)) { ntiles = t + 2; done = true; break; }
    }

    if (!done) {
        // RARE: horizon exceeded. Rebuild full distributed rem from kept words so far.
        unsigned rem0 = 0, rem1 = 0;
        for (int tt = 0; tt < HTILE; tt++) {
            unsigned kw = ~smrem[tt];
            while (kw) {
                int d = __ffs(kw) - 1; kw &= kw - 1;
                const unsigned* row = g_supp + (size_t)(tt * 32 + d) * SUPP_W;
                rem0 |= row[lane]; rem1 |= row[32 + lane];
            }
        }
        for (int t = HTILE; t < N_TILE; t++) {
            int p0 = t * 32;
            unsigned curw = __shfl_sync(F, (t < 32) ? rem0 : rem1, t & 31);
            unsigned mydiag = g_supp[(size_t)(p0 + lane) * SUPP_W + t];
            #pragma unroll
            for (int d = 0; d < 32; d++) {
                unsigned s = __shfl_sync(F, mydiag, d);
                curw |= s & ~bitmask(curw, d);
            }
            unsigned valid = (t < 62) ? 0xffffffffu : 0xffffu;
            unsigned kw = (~curw) & valid;
            if (lane == 0) smrem[t] = curw;
            kc += __popc(kw);
            #pragma unroll 4
            for (int d = 0; d < 32; d++) {
                unsigned mm = bitmask(kw, d);
                const unsigned* row = g_supp + (size_t)(p0 + d) * SUPP_W;
                rem0 |= mm & row[lane]; rem1 |= mm & row[32 + lane];
            }
            if (kc >= PAD) { ntiles = t + 1; break; }
        }
    }
    __syncwarp();

    // Reconstruct kept positions: popc + warp exclusive scan + bit enumerate
    int total = 0;
    #pragma unroll
    for (int rnd = 0; rnd < 2; rnd++) {
        int idx = rnd * 32 + lane;
        unsigned valid = (idx < 62) ? 0xffffffffu : ((idx == 62) ? 0xffffu : 0u);
        unsigned kw = (idx < ntiles) ? ((~smrem[idx]) & valid) : 0u;
        int c = __popc(kw);
        int inc = c;
        #pragma unroll
        for (int o = 1; o < 32; o <<= 1) {
            int v = __shfl_up_sync(0xffffffffu, inc, o);
            if (lane >= o) inc += v;
        }
        int slot = total + inc - c;
        while (kw) {
            int b = __ffs(kw) - 1; kw &= kw - 1;
            if (slot < PAD) g_keptpos[slot] = idx * 32 + b;
            slot++;
        }
        total += __shfl_sync(0xffffffffu, inc, 31);
    }
    if (lane == 31) g_numkept = (total < PAD) ? total : PAD;
}

// ---------------- K5: gather/scatter outputs (DRAM-bound, float4) ----------------
__global__ void k5_out(const float* __restrict__ scores,
                       const float* __restrict__ masks,
                       float* __restrict__ out) {
    int r  = blockIdx.y;
    int nk = g_numkept;
    int src = -1;
    if (r < nk) src = g_sorted[g_keptpos[r]];

    int c = blockIdx.x * blockDim.x + threadIdx.x;
    if (c < MASK_F4) {
        float4 v = make_float4(0.f, 0.f, 0.f, 0.f);
        if (src >= 0)
            v = reinterpret_cast<const float4*>(masks)[(size_t)src * MASK_F4 + c];
        reinterpret_cast<float4*>(out + PAD*4 + PAD*N_CLS)[(size_t)r * MASK_F4 + c] = v;
    }
    if (blockIdx.x == 0) {
        int t = threadIdx.x;
        if (t < 4) {
            float v = 0.f;
            if (src >= 0) v = reinterpret_cast<const float*>(g_boxes)[src*4 + t];
            out[r*4 + t] = v;
        } else if (t < 4 + N_CLS) {
            int cc = t - 4;
            float v = 0.f;
            if (src >= 0) v = scores[(size_t)src * N_CLS + cc];
            out[PAD*4 + r*N_CLS + cc] = v;
        }
    }
}

// ---------------- launch ----------------
extern "C" void kernel_launch(void* const* d_in, const int* in_sizes, int n_in,
                              void* d_out, int out_size) {
    const float* meta    = (const float*)d_in[0];
    const float* deltas  = (const float*)d_in[1];
    const float* props   = (const float*)d_in[2];
    const float* scores  = (const float*)d_in[3];
    const float* masks   = (const float*)d_in[4];
    float* out = (float*)d_out;

    k1_prep<<<(N_PROP * 32 + 255) / 256, 256>>>(meta, deltas, props, scores);
    k2_sort<<<1, 1024>>>();
    k3_supp<<<N_SORT / 16, 256>>>();
    k4_nms<<<1, 32>>>();
    dim3 g5((MASK_F4 + 255) / 256, PAD);
    k5_out<<<g5, 256>>>(scores, masks, out);
}

// round 10
// speedup vs baseline: 1.4788x; 1.2743x over previous
#include <cuda_runtime.h>
#include <cstdint>

#define N_PROP  2000
#define N_CLS   81
#define N_SORT  2048
#define PAD     300
#define MASK_F  63504      // 28*28*81
#define MASK_F4 15876      // MASK_F / 4
#define N_TILE  63         // ceil(N_PROP/32)
#define HTILE   16         // phase-1 horizon: first 512 boxes (closed system)
#define SROWS   512        // HTILE*32
#define SUPP_W2 16         // words per suppression row in phase-1 block
#define IOU_TH  0.5f

// ---------------- device scratch (no allocations allowed) ----------------
__device__ float4 g_boxes[N_PROP];
__device__ unsigned long long g_keys[N_PROP];
__device__ int    g_sorted[N_SORT];
__device__ float4 g_sboxes[N_PROP];
__device__ unsigned g_supp[SROWS * SUPP_W2];       // 512x512-bit phase-1 suppression block
__device__ int    g_keptpos[PAD];
__device__ int    g_numkept;

// ---------------- K1: per-proposal argmax / max-score / box decode ----------------
__global__ void k1_prep(const float* __restrict__ meta,
                        const float* __restrict__ deltas,
                        const float* __restrict__ props,
                        const float* __restrict__ scores) {
    int warp = (blockIdx.x * blockDim.x + threadIdx.x) >> 5;
    int lane = threadIdx.x & 31;
    if (warp >= N_PROP) return;

    const float* sc = scores + (size_t)warp * N_CLS;
    float bv = -1e30f; int bi = N_CLS; float ms = -1e30f;
    for (int c = lane; c < N_CLS; c += 32) {
        float s = sc[c];
        if (s > bv || (s == bv && c < bi)) { bv = s; bi = c; }
        if (c >= 1) ms = fmaxf(ms, s);
    }
    for (int off = 16; off; off >>= 1) {
        float ov = __shfl_down_sync(0xffffffffu, bv, off);
        int   oi = __shfl_down_sync(0xffffffffu, bi, off);
        float om = __shfl_down_sync(0xffffffffu, ms, off);
        if (ov > bv || (ov == bv && oi < bi)) { bv = ov; bi = oi; }
        ms = fmaxf(ms, om);
    }
    if (lane == 0) {
        float H = meta[0], W = meta[1], scale = meta[2];
        float x1 = props[warp*4+0] / scale, y1 = props[warp*4+1] / scale;
        float x2 = props[warp*4+2] / scale, y2 = props[warp*4+3] / scale;
        float a  = x2 - x1, b = y2 - y1;
        float cx = x1 + 0.5f*a, cy = y1 + 0.5f*b;
        const float* d = deltas + (size_t)warp * (4*N_CLS) + 4*bi;
        float pcx = d[0]*a + cx, pcy = d[1]*b + cy;
        float pw  = expf(d[2])*a, ph = expf(d[3])*b;
        float ox1 = fminf(fmaxf(pcx - 0.5f*pw, 0.f), W - 1.f);
        float oy1 = fminf(fmaxf(pcy - 0.5f*ph, 0.f), H - 1.f);
        float ox2 = fminf(fmaxf(pcx + 0.5f*pw, 0.f), W - 1.f);
        float oy2 = fminf(fmaxf(pcy + 0.5f*ph, 0.f), H - 1.f);
        g_boxes[warp] = make_float4(ox1, oy1, ox2, oy2);

        unsigned u = __float_as_uint(ms);
        u = (u & 0x80000000u) ? ~u : (u | 0x80000000u);
        unsigned hi = ~u;
        g_keys[warp] = ((unsigned long long)hi << 32) | (unsigned)warp;
    }
}

// ---------------- K2: single-block bitonic sort, direct pair indexing ----------------
__global__ void k2_sort() {
    __shared__ unsigned long long sk[N_SORT];
    int t = threadIdx.x;
    for (int i = t; i < N_SORT; i += 1024)
        sk[i] = (i < N_PROP) ? g_keys[i] : 0xFFFFFFFFFFFFFFFFull;
    __syncthreads();
    for (int k = 2; k <= N_SORT; k <<= 1) {
        for (int j = k >> 1; j > 0; j >>= 1) {
            int i = ((t & ~(j - 1)) << 1) | (t & (j - 1));
            int p = i | j;
            unsigned long long a = sk[i], b = sk[p];
            bool up = ((i & k) == 0);
            if (up ? (a > b) : (a < b)) { sk[i] = b; sk[p] = a; }
            __syncthreads();
        }
    }
    for (int i = t; i < N_PROP; i += 1024) {
        int idx = (int)(unsigned)(sk[i] & 0xFFFFFFFFull);
        g_sorted[i]  = idx;
        g_sboxes[i]  = g_boxes[idx];
    }
}

// ---------------- K3: phase-1 suppression block (512 rows x 16 words) ----------------
__global__ void k3_supp() {
    __shared__ float sx1[SROWS], sy1[SROWS], sx2[SROWS], sy2[SROWS], sar[SROWS];
    for (int i = threadIdx.x; i < SROWS; i += blockDim.x) {
        float4 bb = g_sboxes[i];
        sx1[i] = bb.x; sy1[i] = bb.y; sx2[i] = bb.z; sy2[i] = bb.w;
        sar[i] = fmaxf(bb.z - bb.x, 0.f) * fmaxf(bb.w - bb.y, 0.f);
    }
    __syncthreads();
    int lane = threadIdx.x & 31;
    int wid  = threadIdx.x >> 5;
    int base = blockIdx.x * 16;           // 16 rows per block, 32 blocks
    for (int task = wid; task < 16 * SUPP_W2; task += 8) {
        int rl = task >> 4;               // local row (0..15)
        int w  = task & 15;               // word (0..15)
        int ri = base + rl;
        int j  = w * 32 + lane;
        bool bit = false;
        if (j > ri) {
            float ix1 = fmaxf(sx1[ri], sx1[j]);
            float iy1 = fmaxf(sy1[ri], sy1[j]);
            float ix2 = fminf(sx2[ri], sx2[j]);
            float iy2 = fminf(sy2[ri], sy2[j]);
            float inter = fmaxf(ix2 - ix1, 0.f) * fmaxf(iy2 - iy1, 0.f);
            float uni   = fmaxf(sar[ri] + sar[j] - inter, 1e-8f);
            bit = inter > IOU_TH * uni;
        }
        unsigned word = __ballot_sync(0xffffffffu, bit);
        if (lane == 0) g_supp[ri * SUPP_W2 + w] = word;
    }
}

// sign-extended single-bit extract: all-ones if bit `pos` of v is set
__device__ __forceinline__ unsigned bitmask(unsigned v, int pos) {
    int m;
    asm("bfe.s32 %0, %1, %2, 1;" : "=r"(m) : "r"(v), "r"(pos));
    return (unsigned)m;
}

// slow-path helper: suppression word w of row r, computed from smem boxes (ballot)
__device__ __forceinline__ unsigned supp_word(const float* bx1, const float* by1,
        const float* bx2, const float* by2, const float* bar, int r, int w, int lane) {
    int j = w * 32 + lane;
    bool bit = false;
    if (j > r) {
        float ix1 = fmaxf(bx1[r], bx1[j]);
        float iy1 = fmaxf(by1[r], by1[j]);
        float ix2 = fminf(bx2[r], bx2[j]);
        float iy2 = fminf(by2[r], by2[j]);
        float inter = fmaxf(ix2 - ix1, 0.f) * fmaxf(iy2 - iy1, 0.f);
        float uni   = fmaxf(bar[r] + bar[j] - inter, 1e-8f);
        bit = inter > IOU_TH * uni;
    }
    return __ballot_sync(0xffffffffu, bit);
}

// ---------------- K4: greedy NMS — register-resident diagonal closure ----------------
// __launch_bounds__(32,1): one warp, full register file. Phase-1 tile loop FULLY
// unrolled so the double-buffered diagonal arrays and rem-update rows stay in
// registers (no spill — verify regs >= 96 in ncu). Serial chain = BFE+LOP3 per box,
// all LDGs prefetched a tile ahead. Rare horizon-overflow path recomputes suppression
// bits on the fly (ballot) — correct on all inputs, never taken on benign data.
__global__ void __launch_bounds__(32, 1) k4_nms() {
    __shared__ unsigned smrem[N_TILE + 1];
    __shared__ float bx1[N_SORT], by1[N_SORT], bx2[N_SORT], by2[N_SORT], bar[N_SORT];
    const unsigned F = 0xffffffffu;
    int lane = threadIdx.x;
    unsigned remlo = 0;                   // lane l<16 owns horizon rem word l (dup in l+16..)
    int kc = 0, ntiles = N_TILE;
    bool done = false;
    int w16 = lane & 15, r0 = lane & 16;

    unsigned d2[2][32];                   // double-buffered diagonal blocks (registers)
    #pragma unroll
    for (int j = 0; j < 32; j++) d2[0][j] = g_supp[j * SUPP_W2];

    #pragma unroll
    for (int t = 0; t < HTILE; t++) {
        if (!done) {
            int p0 = t * 32;
            unsigned ld[16];              // rem-update rows (off-chain LDGs)
            #pragma unroll
            for (int d = 0; d < 16; d++)
                ld[d] = g_supp[(p0 + r0 + d) * SUPP_W2 + w16];
            if (t + 1 < HTILE) {          // prefetch next tile's diagonal words
                #pragma unroll
                for (int d = 0; d < 32; d++)
                    d2[(t + 1) & 1][d] = g_supp[(p0 + 32 + d) * SUPP_W2 + (t + 1)];
            }
            unsigned curw = __shfl_sync(F, remlo, t);   // seed (1 shfl/tile)
            #pragma unroll
            for (int d = 0; d < 32; d++)                // serial closure: BFE+LOP3
                curw |= d2[t & 1][d] & ~bitmask(curw, d);
            unsigned kw = ~curw;
            if (lane == 0) smrem[t] = curw;
            kc += __popc(kw);
            unsigned upd = 0;                           // horizon rem update (off-chain)
            #pragma unroll
            for (int d = 0; d < 16; d++)
                upd |= ld[d] & bitmask(kw, r0 + d);
            upd |= __shfl_xor_sync(F, upd, 16);
            remlo |= upd;
            if (kc >= PAD) { ntiles = t + 1; done = true; }
        }
    }

    if (!done) {
        // RARE: horizon exceeded. Compute suppression on the fly from sorted boxes.
        for (int i = lane; i < N_SORT; i += 32) {
            float4 bb = (i < N_PROP) ? g_sboxes[i] : make_float4(0.f, 0.f, 0.f, 0.f);
            bx1[i] = bb.x; by1[i] = bb.y; bx2[i] = bb.z; by2[i] = bb.w;
            bar[i] = fmaxf(bb.z - bb.x, 0.f) * fmaxf(bb.w - bb.y, 0.f);
        }
        __syncwarp();
        // rebuild full distributed rem (lane owns words lane, lane+32) from kept so far
        unsigned rem0 = 0, rem1 = 0;
        for (int tt = 0; tt < HTILE; tt++) {
            unsigned kw = ~smrem[tt];
            while (kw) {
                int d = __ffs(kw) - 1; kw &= kw - 1;
                int r = tt * 32 + d;
                for (int w = 0; w < 64; w++) {
                    unsigned word = supp_word(bx1, by1, bx2, by2, bar, r, w, lane);
                    if (w < 32) { if (lane == w)      rem0 |= word; }
                    else        { if (lane == w - 32) rem1 |= word; }
                }
            }
        }
        for (int t = HTILE; t < N_TILE; t++) {
            int p0 = t * 32;
            unsigned curw = __shfl_sync(F, (t < 32) ? rem0 : rem1, t & 31);
            for (int d = 0; d < 32; d++) {            // diag word computed just-in-time
                unsigned s = supp_word(bx1, by1, bx2, by2, bar, p0 + d, t, lane);
                curw |= s & ~bitmask(curw, d);
            }
            unsigned valid = (t < 62) ? 0xffffffffu : 0xffffu;
            unsigned kw = (~curw) & valid;
            if (lane == 0) smrem[t] = curw;
            kc += __popc(kw);
            unsigned kwi = kw;
            while (kwi) {                             // rem update for kept rows
                int d = __ffs(kwi) - 1; kwi &= kwi - 1;
                int r = p0 + d;
                for (int w = t; w < 64; w++) {
                    unsigned word = supp_word(bx1, by1, bx2, by2, bar, r, w, lane);
                    if (w < 32) { if (lane == w)      rem0 |= word; }
                    else        { if (lane == w - 32) rem1 |= word; }
                }
            }
            if (kc >= PAD) { ntiles = t + 1; break; }
        }
    }
    __syncwarp();

    // Reconstruct kept positions: popc + warp exclusive scan + bit enumerate
    int total = 0;
    #pragma unroll
    for (int rnd = 0; rnd < 2; rnd++) {
        int idx = rnd * 32 + lane;
        unsigned valid = (idx < 62) ? 0xffffffffu : ((idx == 62) ? 0xffffu : 0u);
        unsigned kw = (idx < ntiles) ? ((~smrem[idx]) & valid) : 0u;
        int c = __popc(kw);
        int inc = c;
        #pragma unroll
        for (int o = 1; o < 32; o <<= 1) {
            int v = __shfl_up_sync(0xffffffffu, inc, o);
            if (lane >= o) inc += v;
        }
        int slot = total + inc - c;
        while (kw) {
            int b = __ffs(kw) - 1; kw &= kw - 1;
            if (slot < PAD) g_keptpos[slot] = idx * 32 + b;
            slot++;
        }
        total += __shfl_sync(0xffffffffu, inc, 31);
    }
    if (lane == 31) g_numkept = (total < PAD) ? total : PAD;
}

// ---------------- K5: gather/scatter outputs (DRAM-bound, float4) ----------------
__global__ void k5_out(const float* __restrict__ scores,
                       const float* __restrict__ masks,
                       float* __restrict__ out) {
    int r  = blockIdx.y;
    int nk = g_numkept;
    int src = -1;
    if (r < nk) src = g_sorted[g_keptpos[r]];

    int c = blockIdx.x * blockDim.x + threadIdx.x;
    if (c < MASK_F4) {
        float4 v = make_float4(0.f, 0.f, 0.f, 0.f);
        if (src >= 0)
            v = reinterpret_cast<const float4*>(masks)[(size_t)src * MASK_F4 + c];
        reinterpret_cast<float4*>(out + PAD*4 + PAD*N_CLS)[(size_t)r * MASK_F4 + c] = v;
    }
    if (blockIdx.x == 0) {
        int t = threadIdx.x;
        if (t < 4) {
            float v = 0.f;
            if (src >= 0) v = reinterpret_cast<const float*>(g_boxes)[src*4 + t];
            out[r*4 + t] = v;
        } else if (t < 4 + N_CLS) {
            int cc = t - 4;
            float v = 0.f;
            if (src >= 0) v = scores[(size_t)src * N_CLS + cc];
            out[PAD*4 + r*N_CLS + cc] = v;
        }
    }
}

// ---------------- launch ----------------
extern "C" void kernel_launch(void* const* d_in, const int* in_sizes, int n_in,
                              void* d_out, int out_size) {
    const float* meta    = (const float*)d_in[0];
    const float* deltas  = (const float*)d_in[1];
    const float* props   = (const float*)d_in[2];
    const float* scores  = (const float*)d_in[3];
    const float* masks   = (const float*)d_in[4];
    float* out = (float*)d_out;

    k1_prep<<<(N_PROP * 32 + 255) / 256, 256>>>(meta, deltas, props, scores);
    k2_sort<<<1, 1024>>>();
    k3_supp<<<SROWS / 16, 256>>>();
    k4_nms<<<1, 32>>>();
    dim3 g5((MASK_F4 + 255) / 256, PAD);
    k5_out<<<g5, 256>>>(scores, masks, out);
}

// round 13
// speedup vs baseline: 1.5152x; 1.0246x over previous
#include <cuda_runtime.h>
#include <cstdint>

#define N_PROP  2000
#define N_CLS   81
#define N_SORT  2048
#define PAD     300
#define MASK_F  63504      // 28*28*81
#define MASK_F4 15876      // MASK_F / 4
#define N_TILE  63         // ceil(N_PROP/32)
#define HTILE   16         // phase-1 horizon: first 512 boxes (closed system)
#define SROWS   512        // HTILE*32
#define SUPP_W2 16         // words per suppression row in phase-1 block
#define IOU_TH  0.5f

// ---------------- device scratch (no allocations allowed) ----------------
__device__ float4 g_boxes[N_PROP];
__device__ unsigned long long g_keys[N_PROP];
__device__ int    g_sorted[N_SORT];
__device__ float4 g_sboxes[N_PROP];
__device__ unsigned g_supp[SROWS * SUPP_W2];       // 512x512-bit phase-1 suppression block
__device__ int    g_keptpos[PAD];
__device__ int    g_numkept;

// ---------------- K1: per-proposal argmax / max-score / box decode ----------------
__global__ void k1_prep(const float* __restrict__ meta,
                        const float* __restrict__ deltas,
                        const float* __restrict__ props,
                        const float* __restrict__ scores) {
    int warp = (blockIdx.x * blockDim.x + threadIdx.x) >> 5;
    int lane = threadIdx.x & 31;
    if (warp >= N_PROP) return;

    const float* sc = scores + (size_t)warp * N_CLS;
    float bv = -1e30f; int bi = N_CLS; float ms = -1e30f;
    for (int c = lane; c < N_CLS; c += 32) {
        float s = sc[c];
        if (s > bv || (s == bv && c < bi)) { bv = s; bi = c; }
        if (c >= 1) ms = fmaxf(ms, s);
    }
    for (int off = 16; off; off >>= 1) {
        float ov = __shfl_down_sync(0xffffffffu, bv, off);
        int   oi = __shfl_down_sync(0xffffffffu, bi, off);
        float om = __shfl_down_sync(0xffffffffu, ms, off);
        if (ov > bv || (ov == bv && oi < bi)) { bv = ov; bi = oi; }
        ms = fmaxf(ms, om);
    }
    if (lane == 0) {
        float H = meta[0], W = meta[1], scale = meta[2];
        float x1 = props[warp*4+0] / scale, y1 = props[warp*4+1] / scale;
        float x2 = props[warp*4+2] / scale, y2 = props[warp*4+3] / scale;
        float a  = x2 - x1, b = y2 - y1;
        float cx = x1 + 0.5f*a, cy = y1 + 0.5f*b;
        const float* d = deltas + (size_t)warp * (4*N_CLS) + 4*bi;
        float pcx = d[0]*a + cx, pcy = d[1]*b + cy;
        float pw  = expf(d[2])*a, ph = expf(d[3])*b;
        float ox1 = fminf(fmaxf(pcx - 0.5f*pw, 0.f), W - 1.f);
        float oy1 = fminf(fmaxf(pcy - 0.5f*ph, 0.f), H - 1.f);
        float ox2 = fminf(fmaxf(pcx + 0.5f*pw, 0.f), W - 1.f);
        float oy2 = fminf(fmaxf(pcy + 0.5f*ph, 0.f), H - 1.f);
        g_boxes[warp] = make_float4(ox1, oy1, ox2, oy2);

        unsigned u = __float_as_uint(ms);
        u = (u & 0x80000000u) ? ~u : (u | 0x80000000u);
        unsigned hi = ~u;
        g_keys[warp] = ((unsigned long long)hi << 32) | (unsigned)warp;
    }
}

// ---------------- K2: warp-register bitonic sort (smem only for j>=64) ----------------
// Thread owns elements i0 = 64*warp + lane and i1 = i0 + 32. Substages with j<=32 run
// in registers: j=32 is an in-thread swap, j<=16 are shfl_xor compare-exchanges.
// Only j>=64 substages (15 of 66) go through shared memory + __syncthreads.
__device__ __forceinline__ unsigned long long ce64(unsigned long long e, int i, int j, int k) {
    unsigned long long p = __shfl_xor_sync(0xffffffffu, e, j);
    bool keepmin = (((i & j) == 0) == ((i & k) == 0));
    unsigned long long mn = (e < p) ? e : p;
    unsigned long long mx = (e < p) ? p : e;
    return keepmin ? mn : mx;
}

__global__ void __launch_bounds__(1024, 1) k2_sort() {
    __shared__ unsigned long long sk[N_SORT];
    int tid = threadIdx.x, lane = tid & 31, warp = tid >> 5;
    int i0 = warp * 64 + lane, i1 = i0 + 32;
    for (int i = tid; i < N_SORT; i += 1024)
        sk[i] = (i < N_PROP) ? g_keys[i] : 0xFFFFFFFFFFFFFFFFull;
    __syncthreads();
    unsigned long long e0 = sk[i0], e1 = sk[i1];

    // k = 2..32 : pure shfl substages
    #pragma unroll
    for (int kb = 1; kb <= 5; kb++) {
        int k = 1 << kb;
        #pragma unroll
        for (int j = 16; j >= 1; j >>= 1) {
            if (j <= (k >> 1)) { e0 = ce64(e0, i0, j, k); e1 = ce64(e1, i1, j, k); }
        }
    }
    // k = 64 : j=32 in-thread, then shfl
    {
        const int k = 64;
        bool up = ((i0 & k) == 0);
        unsigned long long lo = (e0 < e1) ? e0 : e1, hi = (e0 < e1) ? e1 : e0;
        e0 = up ? lo : hi; e1 = up ? hi : lo;
        #pragma unroll
        for (int j = 16; j >= 1; j >>= 1) { e0 = ce64(e0, i0, j, k); e1 = ce64(e1, i1, j, k); }
    }
    // k = 128..2048 : smem substages for j>=64, then register substages
    #pragma unroll
    for (int kb = 7; kb <= 11; kb++) {
        int k = 1 << kb;
        sk[i0] = e0; sk[i1] = e1;
        __syncthreads();
        for (int j = k >> 1; j >= 64; j >>= 1) {
            int i = ((tid & ~(j - 1)) << 1) | (tid & (j - 1));
            int p = i | j;
            unsigned long long a = sk[i], b = sk[p];
            bool up2 = ((i & k) == 0);
            if (up2 ? (a > b) : (a < b)) { sk[i] = b; sk[p] = a; }
            __syncthreads();
        }
        e0 = sk[i0]; e1 = sk[i1];
        bool up = ((i0 & k) == 0);
        unsigned long long lo = (e0 < e1) ? e0 : e1, hi = (e0 < e1) ? e1 : e0;
        e0 = up ? lo : hi; e1 = up ? hi : lo;
        #pragma unroll
        for (int j = 16; j >= 1; j >>= 1) { e0 = ce64(e0, i0, j, k); e1 = ce64(e1, i1, j, k); }
    }
    // outputs straight from registers
    int idx0 = (int)(unsigned)(e0 & 0xFFFFFFFFull);
    int idx1 = (int)(unsigned)(e1 & 0xFFFFFFFFull);
    if (i0 < N_PROP) { g_sorted[i0] = idx0; g_sboxes[i0] = g_boxes[idx0]; }
    if (i1 < N_PROP) { g_sorted[i1] = idx1; g_sboxes[i1] = g_boxes[idx1]; }
}

// ---------------- K3: phase-1 suppression block (512 rows x 16 words) ----------------
__global__ void k3_supp() {
    __shared__ float sx1[SROWS], sy1[SROWS], sx2[SROWS], sy2[SROWS], sar[SROWS];
    for (int i = threadIdx.x; i < SROWS; i += blockDim.x) {
        float4 bb = g_sboxes[i];
        sx1[i] = bb.x; sy1[i] = bb.y; sx2[i] = bb.z; sy2[i] = bb.w;
        sar[i] = fmaxf(bb.z - bb.x, 0.f) * fmaxf(bb.w - bb.y, 0.f);
    }
    __syncthreads();
    int lane = threadIdx.x & 31;
    int wid  = threadIdx.x >> 5;
    int base = blockIdx.x * 16;
    for (int task = wid; task < 16 * SUPP_W2; task += 8) {
        int rl = task >> 4;
        int w  = task & 15;
        int ri = base + rl;
        int j  = w * 32 + lane;
        bool bit = false;
        if (j > ri) {
            float ix1 = fmaxf(sx1[ri], sx1[j]);
            float iy1 = fmaxf(sy1[ri], sy1[j]);
            float ix2 = fminf(sx2[ri], sx2[j]);
            float iy2 = fminf(sy2[ri], sy2[j]);
            float inter = fmaxf(ix2 - ix1, 0.f) * fmaxf(iy2 - iy1, 0.f);
            float uni   = fmaxf(sar[ri] + sar[j] - inter, 1e-8f);
            bit = inter > IOU_TH * uni;
        }
        unsigned word = __ballot_sync(0xffffffffu, bit);
        if (lane == 0) g_supp[ri * SUPP_W2 + w] = word;
    }
}

// sign-extended single-bit extract: all-ones if bit `pos` of v is set
__device__ __forceinline__ unsigned bitmask(unsigned v, int pos) {
    int m;
    asm("bfe.s32 %0, %1, %2, 1;" : "=r"(m) : "r"(v), "r"(pos));
    return (unsigned)m;
}

// slow-path helper: suppression word w of row r, computed from smem boxes (ballot)
__device__ __forceinline__ unsigned supp_word(const float* bx1, const float* by1,
        const float* bx2, const float* by2, const float* bar, int r, int w, int lane) {
    int j = w * 32 + lane;
    bool bit = false;
    if (j > r) {
        float ix1 = fmaxf(bx1[r], bx1[j]);
        float iy1 = fmaxf(by1[r], by1[j]);
        float ix2 = fminf(bx2[r], bx2[j]);
        float iy2 = fminf(by2[r], by2[j]);
        float inter = fmaxf(ix2 - ix1, 0.f) * fmaxf(iy2 - iy1, 0.f);
        float uni   = fmaxf(bar[r] + bar[j] - inter, 1e-8f);
        bit = inter > IOU_TH * uni;
    }
    return __ballot_sync(0xffffffffu, bit);
}

// ---------------- K4: greedy NMS — register closure, everything prefetched a tile ahead ----------------
// Diagonal blocks AND rem-update rows are register-double-buffered and prefetched one tile
// ahead (static addresses; consumed ~600cyc after issue -> latency fully covered). Per-tile
// serial boundary: tree-reduced upd OR (depth 3) + shfl_xor + seed shfl (~90cyc) on top of
// the 32-step BFE+LOP3 closure (~256cyc). Slow path (horizon overflow) recomputes suppression
// on the fly via ballot — correct on all inputs, never taken on benign data.
__global__ void __launch_bounds__(32, 1) k4_nms() {
    __shared__ unsigned smrem[N_TILE + 1];
    __shared__ float bx1[N_SORT], by1[N_SORT], bx2[N_SORT], by2[N_SORT], bar[N_SORT];
    const unsigned F = 0xffffffffu;
    int lane = threadIdx.x;
    unsigned remlo = 0;                   // lane l<16 owns horizon rem word l (dup in l+16..)
    int kc = 0, ntiles = N_TILE;
    bool done = false;
    int w16 = lane & 15, r0 = lane & 16;

    unsigned d2[2][32], l2[2][16];        // double-buffered diag + rem-update rows (registers)
    #pragma unroll
    for (int j = 0; j < 32; j++) d2[0][j] = g_supp[j * SUPP_W2];
    #pragma unroll
    for (int d = 0; d < 16; d++) l2[0][d] = g_supp[(r0 + d) * SUPP_W2 + w16];

    #pragma unroll
    for (int t = 0; t < HTILE; t++) {
        if (!done) {
            int p0 = t * 32;
            if (t + 1 < HTILE) {          // prefetch next tile's diag + rem rows (off-chain)
                #pragma unroll
                for (int d = 0; d < 32; d++)
                    d2[(t + 1) & 1][d] = g_supp[(p0 + 32 + d) * SUPP_W2 + (t + 1)];
                #pragma unroll
                for (int d = 0; d < 16; d++)
                    l2[(t + 1) & 1][d] = g_supp[(p0 + 32 + r0 + d) * SUPP_W2 + w16];
            }
            unsigned curw = __shfl_sync(F, remlo, t);   // seed (1 shfl/tile)
            #pragma unroll
            for (int d = 0; d < 32; d++)                // serial closure: BFE+LOP3
                curw |= d2[t & 1][d] & ~bitmask(curw, d);
            unsigned kw = ~curw;
            if (lane == 0) smrem[t] = curw;
            kc += __popc(kw);
            // horizon rem update — tree-reduced OR (depth 3, off the long chain)
            unsigned u0 = 0, u1 = 0, u2 = 0, u3 = 0;
            #pragma unroll
            for (int d = 0; d < 4; d++) {
                u0 |= l2[t & 1][d]      & bitmask(kw, r0 + d);
                u1 |= l2[t & 1][d + 4]  & bitmask(kw, r0 + d + 4);
                u2 |= l2[t & 1][d + 8]  & bitmask(kw, r0 + d + 8);
                u3 |= l2[t & 1][d + 12] & bitmask(kw, r0 + d + 12);
            }
            unsigned upd = (u0 | u1) | (u2 | u3);
            upd |= __shfl_xor_sync(F, upd, 16);
            remlo |= upd;
            if (kc >= PAD) { ntiles = t + 1; done = true; }
        }
    }

    if (!done) {
        // RARE: horizon exceeded. Compute suppression on the fly from sorted boxes.
        for (int i = lane; i < N_SORT; i += 32) {
            float4 bb = (i < N_PROP) ? g_sboxes[i] : make_float4(0.f, 0.f, 0.f, 0.f);
            bx1[i] = bb.x; by1[i] = bb.y; bx2[i] = bb.z; by2[i] = bb.w;
            bar[i] = fmaxf(bb.z - bb.x, 0.f) * fmaxf(bb.w - bb.y, 0.f);
        }
        __syncwarp();
        unsigned rem0 = 0, rem1 = 0;
        for (int tt = 0; tt < HTILE; tt++) {
            unsigned kw = ~smrem[tt];
            while (kw) {
                int d = __ffs(kw) - 1; kw &= kw - 1;
                int r = tt * 32 + d;
                for (int w = 0; w < 64; w++) {
                    unsigned word = supp_word(bx1, by1, bx2, by2, bar, r, w, lane);
                    if (w < 32) { if (lane == w)      rem0 |= word; }
                    else        { if (lane == w - 32) rem1 |= word; }
                }
            }
        }
        for (int t = HTILE; t < N_TILE; t++) {
            int p0 = t * 32;
            unsigned curw = __shfl_sync(F, (t < 32) ? rem0 : rem1, t & 31);
            for (int d = 0; d < 32; d++) {
                unsigned s = supp_word(bx1, by1, bx2, by2, bar, p0 + d, t, lane);
                curw |= s & ~bitmask(curw, d);
            }
            unsigned valid = (t < 62) ? 0xffffffffu : 0xffffu;
            unsigned kw = (~curw) & valid;
            if (lane == 0) smrem[t] = curw;
            kc += __popc(kw);
            unsigned kwi = kw;
            while (kwi) {
                int d = __ffs(kwi) - 1; kwi &= kwi - 1;
                int r = p0 + d;
                for (int w = t; w < 64; w++) {
                    unsigned word = supp_word(bx1, by1, bx2, by2, bar, r, w, lane);
                    if (w < 32) { if (lane == w)      rem0 |= word; }
                    else        { if (lane == w - 32) rem1 |= word; }
                }
            }
            if (kc >= PAD) { ntiles = t + 1; break; }
        }
    }
    __syncwarp();

    // Reconstruct kept positions: popc + warp exclusive scan + bit enumerate
    int total = 0;
    #pragma unroll
    for (int rnd = 0; rnd < 2; rnd++) {
        int idx = rnd * 32 + lane;
        unsigned valid = (idx < 62) ? 0xffffffffu : ((idx == 62) ? 0xffffu : 0u);
        unsigned kw = (idx < ntiles) ? ((~smrem[idx]) & valid) : 0u;
        int c = __popc(kw);
        int inc = c;
        #pragma unroll
        for (int o = 1; o < 32; o <<= 1) {
            int v = __shfl_up_sync(0xffffffffu, inc, o);
            if (lane >= o) inc += v;
        }
        int slot = total + inc - c;
        while (kw) {
            int b = __ffs(kw) - 1; kw &= kw - 1;
            if (slot < PAD) g_keptpos[slot] = idx * 32 + b;
            slot++;
        }
        total += __shfl_sync(0xffffffffu, inc, 31);
    }
    if (lane == 31) g_numkept = (total < PAD) ? total : PAD;
}

// ---------------- K5: gather/scatter outputs (DRAM-bound, float4) ----------------
__global__ void k5_out(const float* __restrict__ scores,
                       const float* __restrict__ masks,
                       float* __restrict__ out) {
    int r  = blockIdx.y;
    int nk = g_numkept;
    int src = -1;
    if (r < nk) src = g_sorted[g_keptpos[r]];

    int c = blockIdx.x * blockDim.x + threadIdx.x;
    if (c < MASK_F4) {
        float4 v = make_float4(0.f, 0.f, 0.f, 0.f);
        if (src >= 0)
            v = reinterpret_cast<const float4*>(masks)[(size_t)src * MASK_F4 + c];
        reinterpret_cast<float4*>(out + PAD*4 + PAD*N_CLS)[(size_t)r * MASK_F4 + c] = v;
    }
    if (blockIdx.x == 0) {
        int t = threadIdx.x;
        if (t < 4) {
            float v = 0.f;
            if (src >= 0) v = reinterpret_cast<const float*>(g_boxes)[src*4 + t];
            out[r*4 + t] = v;
        } else if (t < 4 + N_CLS) {
            int cc = t - 4;
            float v = 0.f;
            if (src >= 0) v = scores[(size_t)src * N_CLS + cc];
            out[PAD*4 + r*N_CLS + cc] = v;
        }
    }
}

// ---------------- launch ----------------
extern "C" void kernel_launch(void* const* d_in, const int* in_sizes, int n_in,
                              void* d_out, int out_size) {
    const float* meta    = (const float*)d_in[0];
    const float* deltas  = (const float*)d_in[1];
    const float* props   = (const float*)d_in[2];
    const float* scores  = (const float*)d_in[3];
    const float* masks   = (const float*)d_in[4];
    float* out = (float*)d_out;

    k1_prep<<<(N_PROP * 32 + 255) / 256, 256>>>(meta, deltas, props, scores);
    k2_sort<<<1, 1024>>>();
    k3_supp<<<SROWS / 16, 256>>>();
    k4_nms<<<1, 32>>>();
    dim3 g5((MASK_F4 + 255) / 256, PAD);
    k5_out<<<g5, 256>>>(scores, masks, out);
}